// round 1
// baseline (speedup 1.0000x reference)
#include <cuda_runtime.h>
#include <math.h>

// ---------------- problem constants ----------------
#define Bc     4
#define Mc     50000
#define FINc   128
#define FOUTc  128
#define Kc     4
#define Ecap   800000
#define Dc     512              // FIN*B : SpMM row width
#define TOTROWS (Bc*Mc)         // 200000 GEMM rows

// ---------------- device scratch (no allocs allowed) ----------------
__device__ float g_X[Kc][Mc * Dc];     // Chebyshev stack, layout [m][b][f]
__device__ float g_W[512 * 128];       // permuted GEMM weights: [k*128+f][o]
__device__ int   g_rowptr[Mc + 1];
__device__ int   g_cursor[Mc];
__device__ int   g_col[Ecap];
__device__ float g_val[Ecap];
__device__ float g_ssum[Bc * FOUTc];   // column sums for mean
__device__ float g_u[Bc * FOUTc];      // SE gate

// ---------------- 0. zero counters ----------------
__global__ void k_zero() {
    for (int i = blockIdx.x * blockDim.x + threadIdx.x; i < Mc + Bc * FOUTc;
         i += gridDim.x * blockDim.x) {
        if (i < Mc) g_cursor[i] = 0;
        else        g_ssum[i - Mc] = 0.0f;
    }
}

// ---------------- 1. transpose x [B,M,F] -> X0 [M,B,F] ----------------
__global__ void k_transpose(const float* __restrict__ x) {
    const float4* x4  = reinterpret_cast<const float4*>(x);
    float4*       X04 = reinterpret_cast<float4*>(g_X[0]);
    const int N4 = Bc * Mc * 32;   // 6.4M float4
    for (int i = blockIdx.x * blockDim.x + threadIdx.x; i < N4;
         i += gridDim.x * blockDim.x) {
        int m   = i >> 7;          // / 128
        int rem = i & 127;         // b*32 + f4
        int b   = rem >> 5;
        int f4  = rem & 31;
        X04[i] = x4[((size_t)b * Mc + m) * 32 + f4];
    }
}

// ---------------- 2. CSR build ----------------
__global__ void k_count(const int* __restrict__ rows, int E) {
    for (int e = blockIdx.x * blockDim.x + threadIdx.x; e < E;
         e += gridDim.x * blockDim.x)
        atomicAdd(&g_cursor[rows[e]], 1);
}

__global__ void k_scan() {
    __shared__ int s[1024];
    __shared__ int carry_s;
    const int t = threadIdx.x;
    if (t == 0) carry_s = 0;
    __syncthreads();
    const int nch = (Mc + 1023) / 1024;
    for (int c = 0; c < nch; ++c) {
        int i = c * 1024 + t;
        int v = (i < Mc) ? g_cursor[i] : 0;
        s[t] = v;
        __syncthreads();
        #pragma unroll
        for (int off = 1; off < 1024; off <<= 1) {
            int add = (t >= off) ? s[t - off] : 0;
            __syncthreads();
            s[t] += add;
            __syncthreads();
        }
        int carry = carry_s;            // previous chunks' total
        int excl  = s[t] - v + carry;
        if (i < Mc) { g_rowptr[i] = excl; g_cursor[i] = excl; }
        __syncthreads();
        if (t == 0) carry_s = carry + s[1023];
        __syncthreads();
    }
    if (t == 0) g_rowptr[Mc] = carry_s;
}

__global__ void k_scatter(const int* __restrict__ rows,
                          const int* __restrict__ cols,
                          const float* __restrict__ vals, int E) {
    for (int e = blockIdx.x * blockDim.x + threadIdx.x; e < E;
         e += gridDim.x * blockDim.x) {
        int r    = rows[e];
        int slot = atomicAdd(&g_cursor[r], 1);
        g_col[slot] = cols[e];
        g_val[slot] = vals[e];
    }
}

// ---------------- 3. permute GEMM weights ----------------
// logical GEMM K index j = k*128 + f ; original kernel row = f*4 + k
__global__ void k_permW(const float* __restrict__ kern) {
    for (int i = blockIdx.x * blockDim.x + threadIdx.x; i < 512 * 128;
         i += gridDim.x * blockDim.x) {
        int j = i >> 7, o = i & 127;
        int k = j >> 7, f = j & 127;
        g_W[i] = kern[(f * 4 + k) * 128 + o];
    }
}

// ---------------- 4. SpMM: Xout = alpha * (L @ Xin) + beta * Xprev ----------------
// one block (128 threads) per row; each thread owns one float4 of the 512-wide row
__global__ void k_spmm(int kin, int kprev, int kout, float alpha, float beta) {
    const int r = blockIdx.x;
    const int t = threadIdx.x;
    const int p0 = g_rowptr[r];
    const int p1 = g_rowptr[r + 1];
    const float4* Xin = reinterpret_cast<const float4*>(g_X[kin]);

    float4 acc = make_float4(0.f, 0.f, 0.f, 0.f);
    int p = p0;
    for (; p + 1 < p1; p += 2) {
        int   c0 = g_col[p],     c1 = g_col[p + 1];
        float v0 = g_val[p],     v1 = g_val[p + 1];
        float4 xa = Xin[(size_t)c0 * 128 + t];
        float4 xb = Xin[(size_t)c1 * 128 + t];
        acc.x = fmaf(v0, xa.x, fmaf(v1, xb.x, acc.x));
        acc.y = fmaf(v0, xa.y, fmaf(v1, xb.y, acc.y));
        acc.z = fmaf(v0, xa.z, fmaf(v1, xb.z, acc.z));
        acc.w = fmaf(v0, xa.w, fmaf(v1, xb.w, acc.w));
    }
    if (p < p1) {
        int   c0 = g_col[p];
        float v0 = g_val[p];
        float4 xa = Xin[(size_t)c0 * 128 + t];
        acc.x = fmaf(v0, xa.x, acc.x);
        acc.y = fmaf(v0, xa.y, acc.y);
        acc.z = fmaf(v0, xa.z, acc.z);
        acc.w = fmaf(v0, xa.w, acc.w);
    }

    float4 o;
    if (beta != 0.0f) {
        float4 pv = reinterpret_cast<const float4*>(g_X[kprev])[(size_t)r * 128 + t];
        o.x = fmaf(alpha, acc.x, beta * pv.x);
        o.y = fmaf(alpha, acc.y, beta * pv.y);
        o.z = fmaf(alpha, acc.z, beta * pv.z);
        o.w = fmaf(alpha, acc.w, beta * pv.w);
    } else {
        o.x = alpha * acc.x; o.y = alpha * acc.y;
        o.z = alpha * acc.z; o.w = alpha * acc.w;
    }
    reinterpret_cast<float4*>(g_X[kout])[(size_t)r * 128 + t] = o;
}

// ---------------- 5. GEMM 128x128x16 tile, 8x8 microtile, fused ReLU ----------------
// Y[r, o] = relu( sum_j A[r, j] * g_W[j, o] ),  A[r, k*128+f] = g_X[k][m*512 + b*128 + f]
__global__ __launch_bounds__(256, 2)
void k_gemm(float* __restrict__ Y) {
    __shared__ float As[16][128];
    __shared__ float Bs[16][128];

    const int t  = threadIdx.x;
    const int r0 = blockIdx.x * 128;
    const int ry = t >> 4;              // 0..15
    const int rx = t & 15;              // 0..15

    const int arow = t >> 2;            // 0..63
    const int acol = (t & 3) << 2;      // 0,4,8,12
    const int brow = t >> 5;            // 0..7
    const int bcol = (t & 31) << 2;

    long long base1 = -1, base2 = -1;
    {
        int gr = r0 + arow;
        if (gr < TOTROWS) { int bb = gr / Mc; int mm = gr - bb * Mc;
                            base1 = (long long)mm * Dc + bb * FINc; }
        gr = r0 + arow + 64;
        if (gr < TOTROWS) { int bb = gr / Mc; int mm = gr - bb * Mc;
                            base2 = (long long)mm * Dc + bb * FINc; }
    }

    float acc[8][8];
    #pragma unroll
    for (int i = 0; i < 8; ++i)
        #pragma unroll
        for (int j = 0; j < 8; ++j) acc[i][j] = 0.0f;

    for (int it = 0; it < 32; ++it) {
        const int j0 = it << 4;
        const int k  = j0 >> 7;
        const int f0 = j0 & 127;
        const float* Xk = g_X[k];

        float4 a1 = make_float4(0.f,0.f,0.f,0.f);
        float4 a2 = make_float4(0.f,0.f,0.f,0.f);
        if (base1 >= 0) a1 = *reinterpret_cast<const float4*>(Xk + base1 + f0 + acol);
        if (base2 >= 0) a2 = *reinterpret_cast<const float4*>(Xk + base2 + f0 + acol);
        float4 b1 = *reinterpret_cast<const float4*>(g_W + (j0 + brow) * 128 + bcol);
        float4 b2 = *reinterpret_cast<const float4*>(g_W + (j0 + brow + 8) * 128 + bcol);

        __syncthreads();
        As[acol + 0][arow] = a1.x; As[acol + 1][arow] = a1.y;
        As[acol + 2][arow] = a1.z; As[acol + 3][arow] = a1.w;
        As[acol + 0][arow + 64] = a2.x; As[acol + 1][arow + 64] = a2.y;
        As[acol + 2][arow + 64] = a2.z; As[acol + 3][arow + 64] = a2.w;
        *reinterpret_cast<float4*>(&Bs[brow][bcol])     = b1;
        *reinterpret_cast<float4*>(&Bs[brow + 8][bcol]) = b2;
        __syncthreads();

        #pragma unroll
        for (int kk = 0; kk < 16; ++kk) {
            float a[8], bv[8];
            #pragma unroll
            for (int i = 0; i < 8; ++i) a[i]  = As[kk][ry * 8 + i];
            #pragma unroll
            for (int j = 0; j < 8; ++j) bv[j] = Bs[kk][rx * 8 + j];
            #pragma unroll
            for (int i = 0; i < 8; ++i)
                #pragma unroll
                for (int j = 0; j < 8; ++j)
                    acc[i][j] = fmaf(a[i], bv[j], acc[i][j]);
        }
    }

    // epilogue: ReLU + store
    #pragma unroll
    for (int i = 0; i < 8; ++i) {
        int gr = r0 + ry * 8 + i;
        if (gr < TOTROWS) {
            float4 o1, o2;
            o1.x = fmaxf(acc[i][0], 0.f); o1.y = fmaxf(acc[i][1], 0.f);
            o1.z = fmaxf(acc[i][2], 0.f); o1.w = fmaxf(acc[i][3], 0.f);
            o2.x = fmaxf(acc[i][4], 0.f); o2.y = fmaxf(acc[i][5], 0.f);
            o2.z = fmaxf(acc[i][6], 0.f); o2.w = fmaxf(acc[i][7], 0.f);
            float4* yp = reinterpret_cast<float4*>(Y + (size_t)gr * 128 + rx * 8);
            yp[0] = o1; yp[1] = o2;
        }
    }
}

// ---------------- 6. column sums for mean over nodes ----------------
__global__ void k_mean(const float* __restrict__ Y) {
    const int b = blockIdx.y;
    const int t = threadIdx.x;          // column 0..127
    const int m0 = blockIdx.x * 128;
    const int m1 = min(m0 + 128, Mc);
    float acc = 0.0f;
    for (int m = m0; m < m1; ++m)
        acc += Y[((size_t)b * Mc + m) * 128 + t];
    atomicAdd(&g_ssum[b * 128 + t], acc);
}

// ---------------- 7. SE block (tiny) ----------------
__global__ void k_se(const float* __restrict__ Wd, const float* __restrict__ bd,
                     const float* __restrict__ Wu, const float* __restrict__ bu) {
    __shared__ float s[Bc][128];
    __shared__ float d[Bc][16];
    const int t = threadIdx.x;          // 128 threads
    #pragma unroll
    for (int b = 0; b < Bc; ++b)
        s[b][t] = g_ssum[b * 128 + t] * (1.0f / (float)Mc);
    __syncthreads();
    if (t < 64) {
        int b = t >> 4, j = t & 15;
        float z = bd[j];
        for (int f = 0; f < 128; ++f) z = fmaf(s[b][f], Wd[f * 16 + j], z);
        d[b][j] = z / (1.0f + expf(-z));         // swish
    }
    __syncthreads();
    #pragma unroll
    for (int b = 0; b < Bc; ++b) {
        float z = bu[t];
        for (int j = 0; j < 16; ++j) z = fmaf(d[b][j], Wu[j * 128 + t], z);
        g_u[b * 128 + t] = 1.0f / (1.0f + expf(-z));   // sigmoid
    }
}

// ---------------- 8. in-place gated scale ----------------
__global__ void k_scale(float* __restrict__ Y) {
    float4* Y4 = reinterpret_cast<float4*>(Y);
    const int N4 = Bc * Mc * 32;
    for (int i = blockIdx.x * blockDim.x + threadIdx.x; i < N4;
         i += gridDim.x * blockDim.x) {
        int o4 = i & 31;
        int b  = i / (Mc * 32);
        float4 u = reinterpret_cast<const float4*>(g_u)[b * 32 + o4];
        float4 v = Y4[i];
        v.x *= u.x; v.y *= u.y; v.z *= u.z; v.w *= u.w;
        Y4[i] = v;
    }
}

// ---------------- launch ----------------
extern "C" void kernel_launch(void* const* d_in, const int* in_sizes, int n_in,
                              void* d_out, int out_size) {
    const float* x      = (const float*)d_in[0];
    const float* L_vals = (const float*)d_in[1];
    const int*   L_rows = (const int*)  d_in[2];
    const int*   L_cols = (const int*)  d_in[3];
    const float* kern   = (const float*)d_in[4];
    const float* Wd     = (const float*)d_in[5];
    const float* bd     = (const float*)d_in[6];
    const float* Wu     = (const float*)d_in[7];
    const float* bu     = (const float*)d_in[8];
    float* Y = (float*)d_out;
    const int E = in_sizes[1];

    k_zero     <<<256, 256>>>();
    k_transpose<<<2048, 256>>>(x);
    k_count    <<<(E + 255) / 256, 256>>>(L_rows, E);
    k_scan     <<<1, 1024>>>();
    k_scatter  <<<(E + 255) / 256, 256>>>(L_rows, L_cols, L_vals, E);
    k_permW    <<<256, 256>>>(kern);

    k_spmm<<<Mc, 128>>>(0, 0, 1, 1.0f,  0.0f);   // x1 = L x0
    k_spmm<<<Mc, 128>>>(1, 0, 2, 2.0f, -1.0f);   // x2 = 2 L x1 - x0
    k_spmm<<<Mc, 128>>>(2, 1, 3, 2.0f, -1.0f);   // x3 = 2 L x2 - x1

    k_gemm <<<(TOTROWS + 127) / 128, 256>>>(Y);  // y = relu(A @ W), into d_out
    k_mean <<<dim3((Mc + 127) / 128, Bc), 128>>>(Y);
    k_se   <<<1, 128>>>(Wd, bd, Wu, bu);
    k_scale<<<2048, 256>>>(Y);
}

// round 5
// speedup vs baseline: 1.2779x; 1.2779x over previous
#include <cuda_runtime.h>
#include <cuda_bf16.h>
#include <mma.h>
#include <cstdint>
#include <math.h>

using namespace nvcuda;
using u32 = unsigned int;

// ---------------- problem constants ----------------
#define Bc     4
#define Mc     50000
#define FINc   128
#define FOUTc  128
#define Kc     4
#define Ecap   800000
#define Dc     512
#define TOTROWS (Bc*Mc)

// ---------------- device scratch ----------------
__device__ float g_X[Kc][Mc * Dc];          // Chebyshev stack [m][b][f]
__device__ __nv_bfloat16 g_Wh[512 * 128];   // W hi  [k][n], k = kcheb*128+f
__device__ __nv_bfloat16 g_Wl[512 * 128];   // W lo  [k][n]
__device__ int   g_rowptr[Mc + 1];
__device__ int   g_cursor[Mc];
__device__ int   g_blksum[256];
__device__ int   g_col[Ecap];
__device__ float g_val[Ecap];
__device__ float g_ssum[Bc * FOUTc];
__device__ float g_u[Bc * FOUTc];

// ---------------- 0. zero counters ----------------
__global__ void k_zero() {
    for (int i = blockIdx.x * blockDim.x + threadIdx.x; i < Mc + Bc * FOUTc;
         i += gridDim.x * blockDim.x) {
        if (i < Mc) g_cursor[i] = 0;
        else        g_ssum[i - Mc] = 0.0f;
    }
}

// ---------------- 1. transpose x [B,M,F] -> X0 [M,B,F] ----------------
__global__ void k_transpose(const float* __restrict__ x) {
    const float4* x4  = reinterpret_cast<const float4*>(x);
    float4*       X04 = reinterpret_cast<float4*>(g_X[0]);
    const int N4 = Bc * Mc * 32;
    for (int i = blockIdx.x * blockDim.x + threadIdx.x; i < N4;
         i += gridDim.x * blockDim.x) {
        int m   = i >> 7;
        int rem = i & 127;
        int b   = rem >> 5;
        int f4  = rem & 31;
        X04[i] = x4[((size_t)b * Mc + m) * 32 + f4];
    }
}

// ---------------- 2. CSR build ----------------
__global__ void k_count(const int* __restrict__ rows, int E) {
    for (int e = blockIdx.x * blockDim.x + threadIdx.x; e < E;
         e += gridDim.x * blockDim.x)
        atomicAdd(&g_cursor[rows[e]], 1);
}

__global__ void k_scan1() {
    __shared__ int s[256];
    const int t = threadIdx.x;
    const int i = blockIdx.x * 256 + t;
    int v = (i < Mc) ? g_cursor[i] : 0;
    s[t] = v;
    __syncthreads();
    #pragma unroll
    for (int off = 1; off < 256; off <<= 1) {
        int a = (t >= off) ? s[t - off] : 0;
        __syncthreads();
        s[t] += a;
        __syncthreads();
    }
    if (i < Mc) g_rowptr[i] = s[t] - v;
    if (t == 255) g_blksum[blockIdx.x] = s[255];
}

__global__ void k_scan2(int nblk) {
    __shared__ int s[256];
    const int t = threadIdx.x;
    int v = (t < nblk) ? g_blksum[t] : 0;
    s[t] = v;
    __syncthreads();
    #pragma unroll
    for (int off = 1; off < 256; off <<= 1) {
        int a = (t >= off) ? s[t - off] : 0;
        __syncthreads();
        s[t] += a;
        __syncthreads();
    }
    g_blksum[t] = s[t] - v;
    if (t == 255) g_rowptr[Mc] = s[255];
}

__global__ void k_scan3() {
    const int i = blockIdx.x * 256 + threadIdx.x;
    if (i < Mc) {
        int val = g_rowptr[i] + g_blksum[blockIdx.x];
        g_rowptr[i] = val;
        g_cursor[i] = val;
    }
}

__global__ void k_scatter(const int* __restrict__ rows,
                          const int* __restrict__ cols,
                          const float* __restrict__ vals, int E) {
    for (int e = blockIdx.x * blockDim.x + threadIdx.x; e < E;
         e += gridDim.x * blockDim.x) {
        int r    = rows[e];
        int slot = atomicAdd(&g_cursor[r], 1);
        g_col[slot] = cols[e];
        g_val[slot] = vals[e];
    }
}

// ---------------- 3. split weights: W [k][n] bf16 hi/lo ----------------
// k = kcheb*128 + f ; original kernel row = f*4 + kcheb, col = n
__global__ void k_permW(const float* __restrict__ kern) {
    for (int i = blockIdx.x * blockDim.x + threadIdx.x; i < 512 * 128;
         i += gridDim.x * blockDim.x) {
        int k = i >> 7, n = i & 127;
        int kc = k >> 7, f = k & 127;
        float v = kern[(f * 4 + kc) * 128 + n];
        __nv_bfloat16 h = __float2bfloat16_rn(v);
        __nv_bfloat16 l = __float2bfloat16_rn(v - __bfloat162float(h));
        g_Wh[i] = h;
        g_Wl[i] = l;
    }
}

// ---------------- 4. SpMM ----------------
__global__ void k_spmm(int kin, int kprev, int kout, float alpha, float beta) {
    const int r = blockIdx.x;
    const int t = threadIdx.x;
    const int p0 = g_rowptr[r];
    const int p1 = g_rowptr[r + 1];
    const float4* Xin = reinterpret_cast<const float4*>(g_X[kin]);

    float4 acc = make_float4(0.f, 0.f, 0.f, 0.f);
    int p = p0;
    for (; p + 1 < p1; p += 2) {
        int   c0 = g_col[p],     c1 = g_col[p + 1];
        float v0 = g_val[p],     v1 = g_val[p + 1];
        float4 xa = Xin[(size_t)c0 * 128 + t];
        float4 xb = Xin[(size_t)c1 * 128 + t];
        acc.x = fmaf(v0, xa.x, fmaf(v1, xb.x, acc.x));
        acc.y = fmaf(v0, xa.y, fmaf(v1, xb.y, acc.y));
        acc.z = fmaf(v0, xa.z, fmaf(v1, xb.z, acc.z));
        acc.w = fmaf(v0, xa.w, fmaf(v1, xb.w, acc.w));
    }
    if (p < p1) {
        int   c0 = g_col[p];
        float v0 = g_val[p];
        float4 xa = Xin[(size_t)c0 * 128 + t];
        acc.x = fmaf(v0, xa.x, acc.x);
        acc.y = fmaf(v0, xa.y, acc.y);
        acc.z = fmaf(v0, xa.z, acc.z);
        acc.w = fmaf(v0, xa.w, acc.w);
    }

    float4 o;
    if (beta != 0.0f) {
        float4 pv = reinterpret_cast<const float4*>(g_X[kprev])[(size_t)r * 128 + t];
        o.x = fmaf(alpha, acc.x, beta * pv.x);
        o.y = fmaf(alpha, acc.y, beta * pv.y);
        o.z = fmaf(alpha, acc.z, beta * pv.z);
        o.w = fmaf(alpha, acc.w, beta * pv.w);
    } else {
        o.x = alpha * acc.x; o.y = alpha * acc.y;
        o.z = alpha * acc.z; o.w = alpha * acc.w;
    }
    reinterpret_cast<float4*>(g_X[kout])[(size_t)r * 128 + t] = o;
}

// ---------------- 5. wmma bf16 GEMM: Y = relu(A @ W) ----------------
// CTA tile 128(M) x 128(N), K=512 in 32 chunks of 16.
// 8 warps in 4x2 grid: warp (wm, wn) owns rows wm*32..+31, cols wn*64..+63.
// 3-term bf16 compensation: acc += A1*B1 + A1*B2 + A2*B1 (fp32 accumulate).
__device__ __forceinline__ u32 split2(float a, float b, u32& lo2) {
    __nv_bfloat16 ha = __float2bfloat16_rn(a), hb = __float2bfloat16_rn(b);
    __nv_bfloat16 la = __float2bfloat16_rn(a - __bfloat162float(ha));
    __nv_bfloat16 lb = __float2bfloat16_rn(b - __bfloat162float(hb));
    lo2 = ((u32)__bfloat16_as_ushort(lb) << 16) | __bfloat16_as_ushort(la);
    return ((u32)__bfloat16_as_ushort(hb) << 16) | __bfloat16_as_ushort(ha);
}

#define ALD 24     // A smem ldm (16 + 8 pad), multiple of 8
#define BLD 136    // B smem ldm (128 + 8 pad)

__global__ __launch_bounds__(256)
void k_gemm_wmma(float* __restrict__ Y) {
    __shared__ __nv_bfloat16 Ah[128][ALD], Al[128][ALD];
    __shared__ __nv_bfloat16 Bh[16][BLD],  Bl[16][BLD];
    __shared__ long long rowB[128];
    __shared__ float stg[8][16][16];     // per-warp staging for tail CTA (ldm=16, mult of 4)

    const int t   = threadIdx.x;
    const int wid = t >> 5, lid = t & 31;
    const int wm  = wid & 3;             // 0..3 : row group
    const int wn  = wid >> 2;            // 0..1 : col group
    const int r0  = blockIdx.x * 128;
    const bool full = (r0 + 128 <= TOTROWS);

    if (t < 128) {
        int gr = r0 + t;
        long long rb = -1;
        if (gr < TOTROWS) { int b = gr / Mc; int m = gr - b * Mc;
                            rb = (long long)m * Dc + b * FINc; }
        rowB[t] = rb;
    }
    __syncthreads();

    wmma::fragment<wmma::accumulator, 16, 16, 16, float> acc[2][4];
    #pragma unroll
    for (int mi = 0; mi < 2; ++mi)
        #pragma unroll
        for (int ni = 0; ni < 4; ++ni)
            wmma::fill_fragment(acc[mi][ni], 0.0f);

    for (int c = 0; c < 32; ++c) {
        const int kc = c >> 3;
        const int f0 = (c & 7) << 4;
        const float* Xk = g_X[kc];

        // stage A chunk: 128 rows x 16 cols fp32 -> bf16 hi/lo
        #pragma unroll
        for (int idx = t; idx < 512; idx += 256) {
            int row = idx >> 2, c0 = (idx & 3) << 2;
            long long rb = rowB[row];
            float4 v = make_float4(0.f, 0.f, 0.f, 0.f);
            if (rb >= 0) v = *reinterpret_cast<const float4*>(Xk + rb + f0 + c0);
            u32 lo01, lo23;
            u32 hi01 = split2(v.x, v.y, lo01);
            u32 hi23 = split2(v.z, v.w, lo23);
            *reinterpret_cast<uint2*>(&Ah[row][c0]) = make_uint2(hi01, hi23);
            *reinterpret_cast<uint2*>(&Al[row][c0]) = make_uint2(lo01, lo23);
        }
        // stage B chunk: 16 k-rows x 128 n-cols (k-major, coalesced)
        {
            int row = t >> 4, n0 = (t & 15) << 3;
            int go = (c * 16 + row) * 128 + n0;
            *reinterpret_cast<uint4*>(&Bh[row][n0]) =
                *reinterpret_cast<const uint4*>(g_Wh + go);
            *reinterpret_cast<uint4*>(&Bl[row][n0]) =
                *reinterpret_cast<const uint4*>(g_Wl + go);
        }
        __syncthreads();

        wmma::fragment<wmma::matrix_a, 16, 16, 16, __nv_bfloat16, wmma::row_major> ah[2], al[2];
        #pragma unroll
        for (int mi = 0; mi < 2; ++mi) {
            wmma::load_matrix_sync(ah[mi], &Ah[wm * 32 + mi * 16][0], ALD);
            wmma::load_matrix_sync(al[mi], &Al[wm * 32 + mi * 16][0], ALD);
        }
        #pragma unroll
        for (int ni = 0; ni < 4; ++ni) {
            wmma::fragment<wmma::matrix_b, 16, 16, 16, __nv_bfloat16, wmma::row_major> bh, bl;
            wmma::load_matrix_sync(bh, &Bh[0][wn * 64 + ni * 16], BLD);
            wmma::load_matrix_sync(bl, &Bl[0][wn * 64 + ni * 16], BLD);
            #pragma unroll
            for (int mi = 0; mi < 2; ++mi) {
                wmma::mma_sync(acc[mi][ni], ah[mi], bh, acc[mi][ni]);
                wmma::mma_sync(acc[mi][ni], ah[mi], bl, acc[mi][ni]);
                wmma::mma_sync(acc[mi][ni], al[mi], bh, acc[mi][ni]);
            }
        }
        __syncthreads();
    }

    // epilogue: ReLU on fragments, then store
    #pragma unroll
    for (int mi = 0; mi < 2; ++mi)
        #pragma unroll
        for (int ni = 0; ni < 4; ++ni)
            #pragma unroll
            for (int e = 0; e < acc[mi][ni].num_elements; ++e)
                acc[mi][ni].x[e] = fmaxf(acc[mi][ni].x[e], 0.0f);

    if (full) {
        #pragma unroll
        for (int mi = 0; mi < 2; ++mi)
            #pragma unroll
            for (int ni = 0; ni < 4; ++ni) {
                int gr = r0 + wm * 32 + mi * 16;
                int gc = wn * 64 + ni * 16;
                wmma::store_matrix_sync(Y + (size_t)gr * 128 + gc,
                                        acc[mi][ni], 128, wmma::mem_row_major);
            }
    } else {
        // tail CTA: stage each fragment (ldm=16, legal for fp32), guarded copy
        for (int mi = 0; mi < 2; ++mi)
            for (int ni = 0; ni < 4; ++ni) {
                wmma::store_matrix_sync(&stg[wid][0][0], acc[mi][ni], 16,
                                        wmma::mem_row_major);
                __syncwarp();
                int gc = wn * 64 + ni * 16;
                #pragma unroll
                for (int e = lid; e < 256; e += 32) {
                    int rr = e >> 4, cc = e & 15;
                    int gr = r0 + wm * 32 + mi * 16 + rr;
                    if (gr < TOTROWS)
                        Y[(size_t)gr * 128 + gc + cc] = stg[wid][rr][cc];
                }
                __syncwarp();
            }
    }
}

// ---------------- 6. column sums for mean ----------------
__global__ void k_mean(const float* __restrict__ Y) {
    const int b = blockIdx.y;
    const int t = threadIdx.x;
    const int m0 = blockIdx.x * 128;
    const int m1 = min(m0 + 128, Mc);
    float acc = 0.0f;
    for (int m = m0; m < m1; ++m)
        acc += Y[((size_t)b * Mc + m) * 128 + t];
    atomicAdd(&g_ssum[b * 128 + t], acc);
}

// ---------------- 7. SE block ----------------
__global__ void k_se(const float* __restrict__ Wd, const float* __restrict__ bd,
                     const float* __restrict__ Wu, const float* __restrict__ bu) {
    __shared__ float s[Bc][128];
    __shared__ float d[Bc][16];
    const int t = threadIdx.x;
    #pragma unroll
    for (int b = 0; b < Bc; ++b)
        s[b][t] = g_ssum[b * 128 + t] * (1.0f / (float)Mc);
    __syncthreads();
    if (t < 64) {
        int b = t >> 4, j = t & 15;
        float z = bd[j];
        for (int f = 0; f < 128; ++f) z = fmaf(s[b][f], Wd[f * 16 + j], z);
        d[b][j] = z / (1.0f + expf(-z));
    }
    __syncthreads();
    #pragma unroll
    for (int b = 0; b < Bc; ++b) {
        float z = bu[t];
        for (int j = 0; j < 16; ++j) z = fmaf(d[b][j], Wu[j * 128 + t], z);
        g_u[b * 128 + t] = 1.0f / (1.0f + expf(-z));
    }
}

// ---------------- 8. gated scale ----------------
__global__ void k_scale(float* __restrict__ Y) {
    float4* Y4 = reinterpret_cast<float4*>(Y);
    const int N4 = Bc * Mc * 32;
    for (int i = blockIdx.x * blockDim.x + threadIdx.x; i < N4;
         i += gridDim.x * blockDim.x) {
        int o4 = i & 31;
        int b  = i / (Mc * 32);
        float4 u = reinterpret_cast<const float4*>(g_u)[b * 32 + o4];
        float4 v = Y4[i];
        v.x *= u.x; v.y *= u.y; v.z *= u.z; v.w *= u.w;
        Y4[i] = v;
    }
}

// ---------------- launch ----------------
extern "C" void kernel_launch(void* const* d_in, const int* in_sizes, int n_in,
                              void* d_out, int out_size) {
    const float* x      = (const float*)d_in[0];
    const float* L_vals = (const float*)d_in[1];
    const int*   L_rows = (const int*)  d_in[2];
    const int*   L_cols = (const int*)  d_in[3];
    const float* kern   = (const float*)d_in[4];
    const float* Wd     = (const float*)d_in[5];
    const float* bd     = (const float*)d_in[6];
    const float* Wu     = (const float*)d_in[7];
    const float* bu     = (const float*)d_in[8];
    float* Y = (float*)d_out;
    const int E = in_sizes[1];
    const int NSCAN = (Mc + 255) / 256;   // 196

    k_zero     <<<256, 256>>>();
    k_transpose<<<2048, 256>>>(x);
    k_count    <<<(E + 255) / 256, 256>>>(L_rows, E);
    k_scan1    <<<NSCAN, 256>>>();
    k_scan2    <<<1, 256>>>(NSCAN);
    k_scan3    <<<NSCAN, 256>>>();
    k_scatter  <<<(E + 255) / 256, 256>>>(L_rows, L_cols, L_vals, E);
    k_permW    <<<128, 256>>>(kern);

    k_spmm<<<Mc, 128>>>(0, 0, 1, 1.0f,  0.0f);
    k_spmm<<<Mc, 128>>>(1, 0, 2, 2.0f, -1.0f);
    k_spmm<<<Mc, 128>>>(2, 1, 3, 2.0f, -1.0f);

    k_gemm_wmma<<<(TOTROWS + 127) / 128, 256>>>(Y);
    k_mean  <<<dim3((Mc + 127) / 128, Bc), 128>>>(Y);
    k_se    <<<1, 128>>>(Wd, bd, Wu, bu);
    k_scale <<<2048, 256>>>(Y);
}